// round 1
// baseline (speedup 1.0000x reference)
#include <cuda_runtime.h>

#define HH 360
#define WW 720
#define BB 8
#define TX 40
#define TY 24
#define NTHREADS 256
#define NSTEPS 20

// Ping-pong scratch (allocation-free: __device__ globals).
__device__ float g_bufA[BB * HH * WW];
__device__ float g_bufB[BB * HH * WW];

__global__ __launch_bounds__(NTHREADS) void ocean_step_kernel(
    const float* __restrict__ Tin, float* __restrict__ Tout,
    const float* __restrict__ ug, const float* __restrict__ vg,
    const float* __restrict__ lat, const float* __restrict__ lon,
    const float* __restrict__ mask)
{
    __shared__ float sT[(TY + 4) * (TX + 4)];   // T with 2-halo
    __shared__ float sTn[(TY + 2) * (TX + 2)];  // advected field with 1-halo
    __shared__ float sM[(TY + 2) * (TX + 2)];   // mask with 1-halo
    __shared__ float sInv2dx[TY + 2];           // per-row 1/(2*dx)

    const int b  = blockIdx.z;
    const int x0 = blockIdx.x * TX;
    const int y0 = blockIdx.y * TY;
    const int tid = threadIdx.x;

    const float DEG2RAD = 0.017453292519943295f;
    const float R_EARTH = 6371000.0f;
    const float DTC     = 600.0f;

    // Scalar grid constants (all loads L1/L2-cached, negligible)
    const float dlat   = lat[1] - lat[0];
    const float dlon   = lon[1] - lon[0];
    const float dy     = R_EARTH * DEG2RAD * fabsf(dlat);
    const float sign_y = (dlat > 0.0f) ? 1.0f : -1.0f;
    const float sinvdy  = sign_y / dy;
    const float sinv2dy = sign_y / (2.0f * dy);

    // Per-row 1/(2*dx) for the Tn halo rows
    if (tid < TY + 2) {
        int gy = y0 - 1 + tid;
        gy = min(max(gy, 0), HH - 1);
        float la = lat[gy];
        float dx = R_EARTH * DEG2RAD * dlon * cosf(la * DEG2RAD);
        sInv2dx[tid] = 1.0f / (2.0f * dx);
    }

    // ---- Stage 1: load T tile with 2-halo. x wraps (periodic roll);
    //      y clamps (clamped rows are never consumed in a wrong formula).
    const float* Tb = Tin + (size_t)b * HH * WW;
    for (int i = tid; i < (TY + 4) * (TX + 4); i += NTHREADS) {
        int ly = i / (TX + 4), lx = i % (TX + 4);
        int gy = y0 - 2 + ly;
        int gx = x0 - 2 + lx;
        gy = min(max(gy, 0), HH - 1);
        gx += (gx < 0) ? WW : 0;
        gx -= (gx >= WW) ? WW : 0;
        sT[i] = Tb[gy * WW + gx];
    }
    __syncthreads();

    // ---- Stage 2: compute Tn on (TY+2)x(TX+2). Out-of-domain halo -> 0
    //      (this is exactly the conv's zero padding).
    const float* ugb = ug + (size_t)b * HH * WW;
    const float* vgb = vg + (size_t)b * HH * WW;
    for (int i = tid; i < (TY + 2) * (TX + 2); i += NTHREADS) {
        int ly = i / (TX + 2), lx = i % (TX + 2);
        int gy = y0 - 1 + ly;
        int gx = x0 - 1 + lx;
        float val = 0.0f, m = 0.0f;
        if (gy >= 0 && gy < HH && gx >= 0 && gx < WW) {
            int sy = ly + 1, sx = lx + 1;  // into sT (halo offset)
            float c  = sT[sy * (TX + 4) + sx];
            float up = sT[(sy - 1) * (TX + 4) + sx];
            float dn = sT[(sy + 1) * (TX + 4) + sx];
            float lf = sT[sy * (TX + 4) + sx - 1];
            float rt = sT[sy * (TX + 4) + sx + 1];
            float dTdy;
            if (gy == 0)           dTdy = (dn - c) * sinvdy;
            else if (gy == HH - 1) dTdy = (c - up) * sinvdy;
            else                   dTdy = (dn - up) * sinv2dy;
            float dTdx = (rt - lf) * sInv2dx[ly];
            int gidx = gy * WW + gx;
            m = mask[gidx];
            float adv = ugb[(size_t)b * 0 + gidx] * dTdx + vgb[gidx] * dTdy;
            val = c - DTC * adv * m;
        }
        sTn[i] = val;
        sM[i]  = m;
    }
    __syncthreads();

    // ---- Stage 3: 3x3 binomial filter (zero-padded) * mask, write tile.
    float* Ob = Tout + (size_t)b * HH * WW;
    for (int i = tid; i < TY * TX; i += NTHREADS) {
        int oy = i / TX, ox = i % TX;
        int ty = oy + 1, tx = ox + 1;
        const float* t = &sTn[ty * (TX + 2) + tx];
        float s = 4.0f * t[0]
                + 2.0f * (t[-(TX + 2)] + t[(TX + 2)] + t[-1] + t[1])
                + (t[-(TX + 2) - 1] + t[-(TX + 2) + 1]
                 + t[(TX + 2) - 1] + t[(TX + 2) + 1]);
        s *= (1.0f / 16.0f);
        Ob[(y0 + oy) * WW + (x0 + ox)] = s * sM[ty * (TX + 2) + tx];
    }
}

extern "C" void kernel_launch(void* const* d_in, const int* in_sizes, int n_in,
                              void* d_out, int out_size)
{
    const float* T    = (const float*)d_in[0];
    const float* ug   = (const float*)d_in[1];
    const float* vg   = (const float*)d_in[2];
    const float* lat  = (const float*)d_in[3];
    const float* lon  = (const float*)d_in[4];
    const float* mask = (const float*)d_in[5];
    float* out = (float*)d_out;

    float *bufA = nullptr, *bufB = nullptr;
    cudaGetSymbolAddress((void**)&bufA, g_bufA);
    cudaGetSymbolAddress((void**)&bufB, g_bufB);

    dim3 grid(WW / TX, HH / TY, BB);  // 18 x 15 x 8
    dim3 block(NTHREADS);

    const float* cur = T;
    for (int s = 0; s < NSTEPS; s++) {
        float* dst = (s == NSTEPS - 1) ? out : ((s & 1) ? bufB : bufA);
        ocean_step_kernel<<<grid, block>>>(cur, dst, ug, vg, lat, lon, mask);
        cur = dst;
    }
}

// round 2
// speedup vs baseline: 1.2273x; 1.2273x over previous
#include <cuda_runtime.h>

#define HH 360
#define WW 720
#define W2 360            // float2 columns per row
#define BB 8
#define TYB 10            // output rows per block
#define NTH 384           // 12 warps; cols 0..359 active
#define NSTEPS 20

// Ping-pong scratch (allocation-free: __device__ globals).
__device__ float g_bufA[BB * HH * WW];
__device__ float g_bufB[BB * HH * WW];

__global__ __launch_bounds__(NTH) void ocean_step(
    const float* __restrict__ Tin, float* __restrict__ Tout,
    const float* __restrict__ ug, const float* __restrict__ vg,
    const float* __restrict__ lat, const float* __restrict__ lon,
    const float* __restrict__ mask)
{
    __shared__ float sT[2][WW];   // T row ring (for lf/rt periodic scalars)
    __shared__ float sN[2][WW];   // Tn row ring (for filter L/R scalars)

    const int c   = threadIdx.x;       // float2 column index
    const bool act = (c < W2);
    const int y0  = blockIdx.x * TYB;
    const int b   = blockIdx.y;

    const float DEG2RAD = 0.017453292519943295f;
    const float RE  = 6371000.0f;
    const float DTC = 600.0f;

    const float dlat = lat[1] - lat[0];
    const float dlon = lon[1] - lon[0];
    const float dy   = RE * DEG2RAD * fabsf(dlat);
    const float sgn  = (dlat > 0.0f) ? 1.0f : -1.0f;
    const float sinvdy  = sgn / dy;
    const float sinv2dy = sgn / (2.0f * dy);
    const float xden = 2.0f * RE * DEG2RAD * dlon;

    const float2* Tb = (const float2*)(Tin + (size_t)b * HH * WW);
    const float2* ub = (const float2*)(ug  + (size_t)b * HH * WW);
    const float2* vb = (const float2*)(vg  + (size_t)b * HH * WW);
    const float2* mb = (const float2*)mask;
    float2*       Ob = (float2*)(Tout + (size_t)b * HH * WW);

    // Rolling register state
    float2 Tm, Tc, Tp;                       // T rows r-1, r, r+1
    float2 TpL;                              // prefetched T row r+2
    float2 ucur, vcur, mcur;                 // ug/vg/mask at row r
    float2 uL, vL, mL;                       // prefetched row r+1
    float2 mprev;                            // mask at row r-1 (for emit)
    float2 hm, hc, hp;                       // horizontal-pass rows r-2, r-1, r

    hm = make_float2(0.f, 0.f);
    hc = make_float2(0.f, 0.f);
    mprev = make_float2(0.f, 0.f);
    mcur  = make_float2(0.f, 0.f);
    ucur = vcur = make_float2(0.f, 0.f);

    // ---- preload: Tm=T(y0-2), Tc=T(y0-1), prefetch T(y0) and uvm(y0-1)
    if (act) {
        int rm = max(y0 - 2, 0);
        int rc = max(y0 - 1, 0);
        Tm  = Tb[rm * W2 + c];
        Tc  = Tb[rc * W2 + c];
        TpL = Tb[min(y0, HH - 1) * W2 + c];
        ((float2*)sT[(y0 - 1) & 1])[c] = Tc;
        int r1 = y0 - 1;
        if (r1 >= 0) {                        // r1 < HH always
            uL = ub[r1 * W2 + c];
            vL = vb[r1 * W2 + c];
            mL = mb[r1 * W2 + c];
        } else {
            uL = vL = mL = make_float2(0.f, 0.f);
        }
    }
    __syncthreads();

    for (int r = y0 - 1; r <= y0 + TYB; ++r) {
        const bool rvalid = (r >= 0) && (r < HH);

        // consume prefetched values
        Tp = TpL;
        mprev = mcur;
        ucur = uL; vcur = vL; mcur = mL;

        // issue next prefetches (row r+2 for T, row r+1 for uvm)
        if (act) {
            TpL = Tb[min(r + 2, HH - 1) * W2 + c];
            int rn = r + 1;
            if (rn >= 0 && rn < HH) {
                uL = ub[rn * W2 + c];
                vL = vb[rn * W2 + c];
                mL = mb[rn * W2 + c];
            }
        }

        // per-row uniform scalars
        int rl = min(max(r, 0), HH - 1);
        float latr = lat[rl];
        float inv2dx = 1.0f / (xden * __cosf(latr * DEG2RAD));
        float cA, cB, cC;
        if (r == 0)            { cA = sinvdy;  cB = -sinvdy; cC = 0.f; }
        else if (r == HH - 1)  { cA = 0.f;     cB = sinvdy;  cC = -sinvdy; }
        else                   { cA = sinv2dy; cB = 0.f;     cC = -sinv2dy; }

        // stage T row r+1 to shared (needed as Tc next iteration)
        if (act) ((float2*)sT[(r + 1) & 1])[c] = Tp;
        __syncthreads();

        // ---- advection: Tn(r)
        float2 Tn = make_float2(0.f, 0.f);
        if (act && rvalid) {
            const float* rowT = sT[r & 1];
            float lf = rowT[(c == 0)      ? (WW - 1) : (2 * c - 1)];
            float rt = rowT[(c == W2 - 1) ? 0        : (2 * c + 2)];
            float dTdx_x = (Tc.y - lf) * inv2dx;
            float dTdx_y = (rt - Tc.x) * inv2dx;
            float dTdy_x = cA * Tp.x + cB * Tc.x + cC * Tm.x;
            float dTdy_y = cA * Tp.y + cB * Tc.y + cC * Tm.y;
            Tn.x = Tc.x - DTC * (ucur.x * dTdx_x + vcur.x * dTdy_x) * mcur.x;
            Tn.y = Tc.y - DTC * (ucur.y * dTdx_y + vcur.y * dTdy_y) * mcur.y;
        }
        if (act) ((float2*)sN[r & 1])[c] = Tn;
        __syncthreads();

        // ---- horizontal filter pass h(r) = (1,2,1) with zero x-padding
        if (act) {
            const float* rowN = sN[r & 1];
            float L = (c == 0)      ? 0.f : rowN[2 * c - 1];
            float R = (c == W2 - 1) ? 0.f : rowN[2 * c + 2];
            hp.x = L    + 2.f * Tn.x + Tn.y;
            hp.y = Tn.x + 2.f * Tn.y + R;

            // ---- vertical pass + mask: emit output row y = r-1
            int y = r - 1;
            if (y >= y0) {           // y < y0+TYB guaranteed by loop range
                float2 o;
                o.x = (hm.x + 2.f * hc.x + hp.x) * 0.0625f * mprev.x;
                o.y = (hm.y + 2.f * hc.y + hp.y) * 0.0625f * mprev.y;
                Ob[y * W2 + c] = o;
            }
        }

        // roll registers
        Tm = Tc; Tc = Tp;
        hm = hc; hc = hp;
    }
}

extern "C" void kernel_launch(void* const* d_in, const int* in_sizes, int n_in,
                              void* d_out, int out_size)
{
    const float* T    = (const float*)d_in[0];
    const float* ug   = (const float*)d_in[1];
    const float* vg   = (const float*)d_in[2];
    const float* lat  = (const float*)d_in[3];
    const float* lon  = (const float*)d_in[4];
    const float* mask = (const float*)d_in[5];
    float* out = (float*)d_out;

    float *bufA = nullptr, *bufB = nullptr;
    cudaGetSymbolAddress((void**)&bufA, g_bufA);
    cudaGetSymbolAddress((void**)&bufB, g_bufB);

    dim3 grid(HH / TYB, BB);   // 36 x 8 = 288 blocks
    dim3 block(NTH);

    const float* cur = T;
    for (int s = 0; s < NSTEPS; s++) {
        float* dst = (s == NSTEPS - 1) ? out : ((s & 1) ? bufB : bufA);
        ocean_step<<<grid, block>>>(cur, dst, ug, vg, lat, lon, mask);
        cur = dst;
    }
}

// round 3
// speedup vs baseline: 1.2935x; 1.0539x over previous
#include <cuda_runtime.h>

#define HH 360
#define WW 720
#define W2 360            // float2 columns per row
#define BB 8
#define TYS 10            // output rows per block
#define XT  120           // active float2 columns per block
#define NSTEPS 20

// Ping-pong scratch (allocation-free: __device__ globals).
__device__ float g_bufA[BB * HH * WW];
__device__ float g_bufB[BB * HH * WW];

__global__ __launch_bounds__(128) void ocean_step(
    const float* __restrict__ Tin, float* __restrict__ Tout,
    const float* __restrict__ ug, const float* __restrict__ vg,
    const float* __restrict__ lat, const float* __restrict__ lon,
    const float* __restrict__ mask)
{
    __shared__ float sInv[TYS + 2];   // per-row 1/(2*dx), rows y0-1 .. y0+TYS

    const int tid = threadIdx.x;
    const int y0  = blockIdx.y * TYS;
    const int b   = blockIdx.z;
    const int c0  = blockIdx.x * XT + tid;   // this thread's float2 column

    const float DEG2RAD = 0.017453292519943295f;
    const float RE  = 6371000.0f;
    const float DTC = 600.0f;

    const float dlat = lat[1] - lat[0];
    const float dlon = lon[1] - lon[0];
    const float dy   = RE * DEG2RAD * fabsf(dlat);
    const float sgn  = (dlat > 0.0f) ? 1.0f : -1.0f;
    const float sinvdy  = sgn / dy;
    const float sinv2dy = sgn / (2.0f * dy);
    const float xden = 2.0f * RE * DEG2RAD * dlon;

    if (tid < TYS + 2) {
        int r  = y0 - 1 + tid;
        int rl = min(max(r, 0), HH - 1);
        sInv[tid] = 1.0f / (xden * __cosf(lat[rl] * DEG2RAD));
    }
    __syncthreads();           // the ONLY barrier in the kernel

    if (tid >= XT) return;

    // periodic x neighbors (float2 granularity)
    const int cm1 = (c0 == 0)      ? (W2 - 1) : (c0 - 1);
    const int cp1 = (c0 == W2 - 1) ? 0        : (c0 + 1);
    const bool leftok  = (c0 > 0);          // Tn at col 2c-1 exists (conv zero-pads x)
    const bool rightok = (c0 < W2 - 1);     // Tn at col 2c+2 exists

    const float2* Tb = (const float2*)(Tin + (size_t)b * HH * WW);
    const float2* ub = (const float2*)(ug  + (size_t)b * HH * WW);
    const float2* vb = (const float2*)(vg  + (size_t)b * HH * WW);
    const float2* mb = (const float2*)mask;
    float2*       Ob = (float2*)(Tout + (size_t)b * HH * WW);

    // T rows: each row held as 3 float2 = cols 2c-2 .. 2c+3 (wrapped)
    float2 Tm_a, Tm_b, Tm_c;     // row r-1
    float2 Tc_a, Tc_b, Tc_c;     // row r
    float2 Tp_a, Tp_b, Tp_c;     // row r+1
    float2 Pf_a, Pf_b, Pf_c;     // prefetch row r+2

    // u/v/m prefetch (row r+1): 3 float2 each
    float2 uPa, uPb, uPc, vPa, vPb, vPc, mPa, mPb, mPc;

    float2 hm = make_float2(0.f, 0.f);
    float2 hc = make_float2(0.f, 0.f);
    float  m_0 = 0.f, m_1 = 0.f;     // mask row r at cols 2c,2c+1

    // ---- preamble
    {
        int rm = max(y0 - 2, 0);
        int rc = max(y0 - 1, 0);
        const float2* Rm = Tb + (size_t)rm * W2;
        const float2* Rc = Tb + (size_t)rc * W2;
        const float2* Rp = Tb + (size_t)min(y0, HH - 1) * W2;
        Tm_a = Rm[cm1]; Tm_b = Rm[c0]; Tm_c = Rm[cp1];
        Tc_a = Rc[cm1]; Tc_b = Rc[c0]; Tc_c = Rc[cp1];
        Pf_a = Rp[cm1]; Pf_b = Rp[c0]; Pf_c = Rp[cp1];
        int r1 = max(y0 - 1, 0);
        const float2* U = ub + (size_t)r1 * W2;
        const float2* V = vb + (size_t)r1 * W2;
        const float2* M = mb + (size_t)r1 * W2;
        uPa = U[cm1]; uPb = U[c0]; uPc = U[cp1];
        vPa = V[cm1]; vPb = V[c0]; vPc = V[cp1];
        mPa = M[cm1]; mPb = M[c0]; mPc = M[cp1];
    }

    #pragma unroll 1
    for (int r = y0 - 1; r <= y0 + TYS; ++r) {
        // consume prefetches
        Tp_a = Pf_a; Tp_b = Pf_b; Tp_c = Pf_c;
        const float mp0 = m_0, mp1 = m_1;           // mask row r-1 (for output)
        const float u_m1 = uPa.y, u_0 = uPb.x, u_1 = uPb.y, u_2 = uPc.x;
        const float v_m1 = vPa.y, v_0 = vPb.x, v_1 = vPb.y, v_2 = vPc.x;
        const float mk_m1 = mPa.y, mk_2 = mPc.x;
        m_0 = mPb.x; m_1 = mPb.y;

        // issue next prefetches
        {
            const float2* Rn = Tb + (size_t)min(r + 2, HH - 1) * W2;
            Pf_a = Rn[cm1]; Pf_b = Rn[c0]; Pf_c = Rn[cp1];
            int rn = min(max(r + 1, 0), HH - 1);
            const float2* U = ub + (size_t)rn * W2;
            const float2* V = vb + (size_t)rn * W2;
            const float2* M = mb + (size_t)rn * W2;
            uPa = U[cm1]; uPb = U[c0]; uPc = U[cp1];
            vPa = V[cm1]; vPb = V[c0]; vPc = V[cp1];
            mPa = M[cm1]; mPb = M[c0]; mPc = M[cp1];
        }

        float2 hp = make_float2(0.f, 0.f);
        if (r >= 0 && r < HH) {
            const float inv2dx = sInv[r - (y0 - 1)];
            float cA, cB, cC;
            if (r == 0)           { cA = sinvdy;  cB = -sinvdy; cC = 0.f; }
            else if (r == HH - 1) { cA = 0.f;     cB = sinvdy;  cC = -sinvdy; }
            else                  { cA = sinv2dy; cB = 0.f;     cC = -sinv2dy; }

            // advection at 4 columns 2c-1 .. 2c+2 (recompute neighbors)
            // col 2c-1
            float dTdx = (Tc_b.x - Tc_a.x) * inv2dx;
            float dTdy = cA * Tp_a.y + cB * Tc_a.y + cC * Tm_a.y;
            float Tn_m = Tc_a.y - DTC * (u_m1 * dTdx + v_m1 * dTdy) * mk_m1;
            Tn_m = leftok ? Tn_m : 0.f;
            // col 2c
            dTdx = (Tc_b.y - Tc_a.y) * inv2dx;
            dTdy = cA * Tp_b.x + cB * Tc_b.x + cC * Tm_b.x;
            const float Tn_0 = Tc_b.x - DTC * (u_0 * dTdx + v_0 * dTdy) * m_0;
            // col 2c+1
            dTdx = (Tc_c.x - Tc_b.x) * inv2dx;
            dTdy = cA * Tp_b.y + cB * Tc_b.y + cC * Tm_b.y;
            const float Tn_1 = Tc_b.y - DTC * (u_1 * dTdx + v_1 * dTdy) * m_1;
            // col 2c+2
            dTdx = (Tc_c.y - Tc_b.y) * inv2dx;
            dTdy = cA * Tp_c.x + cB * Tc_c.x + cC * Tm_c.x;
            float Tn_2 = Tc_c.x - DTC * (u_2 * dTdx + v_2 * dTdy) * mk_2;
            Tn_2 = rightok ? Tn_2 : 0.f;

            // horizontal (1,2,1) pass
            hp.x = Tn_m + 2.f * Tn_0 + Tn_1;
            hp.y = Tn_0 + 2.f * Tn_1 + Tn_2;
        }

        // vertical (1,2,1)/16 * mask : emit output row y = r-1
        const int y = r - 1;
        if (y >= y0) {   // y < y0+TYS guaranteed by loop bound
            float2 o;
            o.x = (hm.x + 2.f * hc.x + hp.x) * 0.0625f * mp0;
            o.y = (hm.y + 2.f * hc.y + hp.y) * 0.0625f * mp1;
            Ob[(size_t)y * W2 + c0] = o;
        }

        // roll
        Tm_a = Tc_a; Tm_b = Tc_b; Tm_c = Tc_c;
        Tc_a = Tp_a; Tc_b = Tp_b; Tc_c = Tp_c;
        hm = hc; hc = hp;
    }
}

extern "C" void kernel_launch(void* const* d_in, const int* in_sizes, int n_in,
                              void* d_out, int out_size)
{
    const float* T    = (const float*)d_in[0];
    const float* ug   = (const float*)d_in[1];
    const float* vg   = (const float*)d_in[2];
    const float* lat  = (const float*)d_in[3];
    const float* lon  = (const float*)d_in[4];
    const float* mask = (const float*)d_in[5];
    float* out = (float*)d_out;

    float *bufA = nullptr, *bufB = nullptr;
    cudaGetSymbolAddress((void**)&bufA, g_bufA);
    cudaGetSymbolAddress((void**)&bufB, g_bufB);

    dim3 grid(W2 / XT, HH / TYS, BB);   // 3 x 36 x 8 = 864 blocks
    dim3 block(128);

    const float* cur = T;
    for (int s = 0; s < NSTEPS; s++) {
        float* dst = (s == NSTEPS - 1) ? out : ((s & 1) ? bufB : bufA);
        ocean_step<<<grid, block>>>(cur, dst, ug, vg, lat, lon, mask);
        cur = dst;
    }
}

// round 4
// speedup vs baseline: 2.1389x; 1.6536x over previous
#include <cuda_runtime.h>

#define HH 360
#define WW 720
#define W2 360            // float2 columns per row
#define BB 8
#define TYS 10            // output rows per warp-band
#define SEG 30            // output float2 cols per warp (lanes 1..30)
#define NSTEPS 20
#define FULLM 0xffffffffu

// Ping-pong scratch (allocation-free: __device__ globals).
__device__ float g_bufA[BB * HH * WW];
__device__ float g_bufB[BB * HH * WW];

__global__ __launch_bounds__(128) void ocean_step(
    const float* __restrict__ Tin, float* __restrict__ Tout,
    const float* __restrict__ ug, const float* __restrict__ vg,
    const float* __restrict__ lat, const float* __restrict__ lon,
    const float* __restrict__ mask)
{
    __shared__ float sInv[TYS + 2];   // per-row 1/(2*dx), rows y0-1 .. y0+TYS

    const int tid  = threadIdx.x;
    const int lane = tid & 31;
    const int wib  = tid >> 5;                  // warp in block (0..3)
    const int y0   = blockIdx.y * TYS;
    const int b    = blockIdx.z;
    const int wg   = blockIdx.x * 4 + wib;      // global warp segment 0..11

    const float DEG2RAD = 0.017453292519943295f;
    const float RE  = 6371000.0f;
    const float DTC = 600.0f;

    const float dlat = lat[1] - lat[0];
    const float dlon = lon[1] - lon[0];
    const float dy   = RE * DEG2RAD * fabsf(dlat);
    const float sgn  = (dlat > 0.0f) ? 1.0f : -1.0f;
    const float sinvdy  = sgn / dy;
    const float sinv2dy = sgn / (2.0f * dy);
    const float xden = 2.0f * RE * DEG2RAD * dlon;

    if (tid < TYS + 2) {
        int r  = y0 - 1 + tid;
        int rl = min(max(r, 0), HH - 1);
        sInv[tid] = 1.0f / (xden * __cosf(lat[rl] * DEG2RAD));
    }
    __syncthreads();

    // lane -> float2 column (wrapped). Lanes 1..SEG emit; 0 and 31 are halo.
    int c = wg * SEG - 1 + lane;
    c = (c < 0) ? c + W2 : ((c >= W2) ? c - W2 : c);
    const bool emit = (lane >= 1) && (lane <= SEG);
    const bool zL = (c == 0);          // filter zero-pad on left of col 0
    const bool zR = (c == W2 - 1);     // filter zero-pad right of col 719

    const float2* Tb = (const float2*)(Tin + (size_t)b * HH * WW);
    const float2* ub = (const float2*)(ug  + (size_t)b * HH * WW);
    const float2* vb = (const float2*)(vg  + (size_t)b * HH * WW);
    const float2* mb = (const float2*)mask;
    float2*       Ob = (float2*)(Tout + (size_t)b * HH * WW);

    float2 Tm, Tc, Tp, Pf;             // T rows r-1, r, r+1, prefetch r+2
    float2 uP, vP, mP;                 // prefetched u/v/m row r+1
    float2 hm = make_float2(0.f, 0.f);
    float2 hc = make_float2(0.f, 0.f);
    float  m_0 = 0.f, m_1 = 0.f;       // mask row r

    // ---- preamble
    {
        int rm = max(y0 - 2, 0);
        int rc = max(y0 - 1, 0);
        Tm = Tb[(size_t)rm * W2 + c];
        Tc = Tb[(size_t)rc * W2 + c];
        Pf = Tb[(size_t)min(y0, HH - 1) * W2 + c];
        int r1 = max(y0 - 1, 0);
        uP = ub[(size_t)r1 * W2 + c];
        vP = vb[(size_t)r1 * W2 + c];
        mP = mb[(size_t)r1 * W2 + c];
    }

    #pragma unroll
    for (int k = 0; k < TYS + 2; ++k) {
        const int r = y0 - 1 + k;

        // consume prefetches
        Tp = Pf;
        const float2 ucur = uP, vcur = vP, mcur = mP;
        const float mp0 = m_0, mp1 = m_1;     // mask row r-1 (for emit)
        m_0 = mcur.x; m_1 = mcur.y;

        // issue next prefetches (T row r+2, u/v/m row r+1)
        {
            int rT = min(r + 2, HH - 1);
            Pf = Tb[(size_t)rT * W2 + c];
            int rn = min(max(r + 1, 0), HH - 1);
            uP = ub[(size_t)rn * W2 + c];
            vP = vb[(size_t)rn * W2 + c];
            mP = mb[(size_t)rn * W2 + c];
        }

        float2 hp = make_float2(0.f, 0.f);
        if (r >= 0 && r < HH) {               // warp-uniform branch
            const float inv2dx = sInv[k];
            const float cA = (r == 0) ? sinvdy  : ((r == HH - 1) ? 0.f      : sinv2dy);
            const float cB = (r == 0) ? -sinvdy : ((r == HH - 1) ? sinvdy   : 0.f);
            const float cC = (r == 0) ? 0.f     : ((r == HH - 1) ? -sinvdy  : -sinv2dy);

            const float lf = __shfl_up_sync(FULLM, Tc.y, 1);   // T[2c-1]
            const float rt = __shfl_down_sync(FULLM, Tc.x, 1); // T[2c+2]

            const float dTdx0 = (Tc.y - lf) * inv2dx;
            const float dTdx1 = (rt - Tc.x) * inv2dx;
            const float dTdy0 = cA * Tp.x + cB * Tc.x + cC * Tm.x;
            const float dTdy1 = cA * Tp.y + cB * Tc.y + cC * Tm.y;

            float2 Tn;
            Tn.x = Tc.x - DTC * (ucur.x * dTdx0 + vcur.x * dTdy0) * m_0;
            Tn.y = Tc.y - DTC * (ucur.y * dTdx1 + vcur.y * dTdy1) * m_1;

            float Tn_m = __shfl_up_sync(FULLM, Tn.y, 1);   // Tn[2c-1]
            float Tn_2 = __shfl_down_sync(FULLM, Tn.x, 1); // Tn[2c+2]
            Tn_m = zL ? 0.f : Tn_m;
            Tn_2 = zR ? 0.f : Tn_2;

            hp.x = Tn_m + 2.f * Tn.x + Tn.y;
            hp.y = Tn.x + 2.f * Tn.y + Tn_2;
        }

        // vertical (1,2,1)/16 * mask : emit output row y = r-1
        const int y = r - 1;
        if (emit && y >= y0) {                // y < y0+TYS by loop bound
            float2 o;
            o.x = (hm.x + 2.f * hc.x + hp.x) * 0.0625f * mp0;
            o.y = (hm.y + 2.f * hc.y + hp.y) * 0.0625f * mp1;
            Ob[(size_t)y * W2 + c] = o;
        }

        // roll (renamed away by full unroll)
        Tm = Tc; Tc = Tp;
        hm = hc; hc = hp;
    }
}

extern "C" void kernel_launch(void* const* d_in, const int* in_sizes, int n_in,
                              void* d_out, int out_size)
{
    const float* T    = (const float*)d_in[0];
    const float* ug   = (const float*)d_in[1];
    const float* vg   = (const float*)d_in[2];
    const float* lat  = (const float*)d_in[3];
    const float* lon  = (const float*)d_in[4];
    const float* mask = (const float*)d_in[5];
    float* out = (float*)d_out;

    float *bufA = nullptr, *bufB = nullptr;
    cudaGetSymbolAddress((void**)&bufA, g_bufA);
    cudaGetSymbolAddress((void**)&bufB, g_bufB);

    dim3 grid(3, HH / TYS, BB);   // 3 x 36 x 8 = 864 blocks (12 warp segments/row)
    dim3 block(128);

    const float* cur = T;
    for (int s = 0; s < NSTEPS; s++) {
        float* dst = (s == NSTEPS - 1) ? out : ((s & 1) ? bufB : bufA);
        ocean_step<<<grid, block>>>(cur, dst, ug, vg, lat, lon, mask);
        cur = dst;
    }
}

// round 5
// speedup vs baseline: 2.3837x; 1.1145x over previous
#include <cuda_runtime.h>

#define HH 360
#define WW 720
#define W2 360
#define BB 8
#define TYS 12
#define NITER (TYS + 6)
#define SEGS 13          // 13*28 = 364 >= 360 float2 cols (wrapped, dup writes benign)
#define EMITW 28
#define BANDS (HH / TYS) // 30
#define NSTEPS 20
#define FULLM 0xffffffffu

// Ping-pong scratch (allocation-free: __device__ globals).
__device__ float g_bufA[BB * HH * WW];
__device__ float g_bufB[BB * HH * WW];

__device__ __forceinline__ float2 f2z() { return make_float2(0.f, 0.f); }

// One kernel = TWO timesteps (advection + 3x3 binomial filter, twice).
// 6-stage rolling pipeline in y; x neighbors via warp shuffles with 2 halo
// lanes per side. No shared memory, no barriers.
__global__ __launch_bounds__(128) void ocean_step2(
    const float* __restrict__ Tin, float* __restrict__ Tout,
    const float* __restrict__ ug, const float* __restrict__ vg,
    const float* __restrict__ lat, const float* __restrict__ lon,
    const float* __restrict__ mask)
{
    const int tid  = threadIdx.x;
    const int lane = tid & 31;
    const int ws   = blockIdx.x * 4 + (tid >> 5);
    const int seg  = ws % SEGS;
    const int rem  = ws / SEGS;
    const int band = rem % BANDS;
    const int b    = rem / BANDS;
    const int y0   = band * TYS;

    // lane -> float2 column (wrapped). Lanes 2..29 emit.
    int c = seg * EMITW - 2 + lane;
    c += (c < 0) ? W2 : 0;
    c -= (c >= W2) ? W2 : 0;
    const bool emitl = (lane >= 2) && (lane <= 29);
    const bool zL = (c == 0);          // conv zero-pad left of scalar col 0
    const bool zR = (c == W2 - 1);     // conv zero-pad right of scalar col 719

    const float DEG2RAD = 0.017453292519943295f;
    const float RE = 6371000.0f, DTC = 600.0f;
    const float dlat = lat[1] - lat[0];
    const float dlon = lon[1] - lon[0];
    const float dy   = RE * DEG2RAD * fabsf(dlat);
    const float sgn  = (dlat > 0.f) ? 1.f : -1.f;
    const float sdy  = sgn / dy;
    const float s2dy = sgn / (2.f * dy);
    const float xden = 2.f * RE * DEG2RAD * dlon;

    const float2* Tb = (const float2*)(Tin + (size_t)b * HH * WW);
    const float2* ub = (const float2*)(ug  + (size_t)b * HH * WW);
    const float2* vb = (const float2*)(vg  + (size_t)b * HH * WW);
    const float2* mb = (const float2*)mask;
    float2*       Ob = (float2*)(Tout + (size_t)b * HH * WW);

    // Rings (fully unrolled loop -> register renames, no MOV cost)
    float2 T0, T1, T2;                          // T rows rA-1, rA, rA+1
    float2 h1a = f2z(), h1b = f2z(), h1c = f2z();   // h1 rows rA-2..rA
    float2 F1a = f2z(), F1b = f2z(), F1c = f2z();   // F1 rows rF-2..rF
    float2 h2a = f2z(), h2b = f2z(), h2c = f2z();   // h2 rows rB-2..rB
    float2 uA = f2z(), u1 = f2z(), u2 = f2z();      // u rows rA, rA-1, rA-2
    float2 vA = f2z(), v1 = f2z(), v2 = f2z();
    float2 mA = f2z(), m1 = f2z(), m2 = f2z(), m3 = f2z();  // mask rA..rA-3
    float  iA = 0.f, i1 = 0.f, i2 = 0.f;            // 1/(2dx) rows rA..rA-2

    T0 = Tb[(size_t)max(y0 - 4, 0) * W2 + c];
    T1 = Tb[(size_t)max(y0 - 3, 0) * W2 + c];

#pragma unroll
    for (int k = 0; k < NITER; ++k) {
        const int rL = y0 - 2 + k;          // T row loaded this iter
        const int rA = rL - 1;              // step-1 advection row
        const int rF = rL - 2;              // step-1 output row
        const int rB = rL - 3;              // step-2 advection row
        const int rE = rL - 4;              // final emit row

        // ring shifts + fresh loads
        m3 = m2; m2 = m1; m1 = mA;
        u2 = u1; u1 = uA;
        v2 = v1; v1 = vA;
        i2 = i1; i1 = iA;
        {
            const int ru = min(max(rA, 0), HH - 1);
            uA = ub[(size_t)ru * W2 + c];
            vA = vb[(size_t)ru * W2 + c];
            mA = mb[(size_t)ru * W2 + c];
            iA = __fdividef(1.f, xden * __cosf(lat[ru] * DEG2RAD));
            T2 = Tb[(size_t)min(max(rL, 0), HH - 1) * W2 + c];
        }

        // ---- stage 1: advection step 1 + horizontal (1,2,1) at row rA
        h1a = h1b; h1b = h1c;
        if (rA >= 0 && rA < HH) {           // warp-uniform branch
            const float cA = (rA == 0) ? sdy  : ((rA == HH - 1) ? 0.f  : s2dy);
            const float cB = (rA == 0) ? -sdy : ((rA == HH - 1) ? sdy  : 0.f);
            const float cC = (rA == 0) ? 0.f  : ((rA == HH - 1) ? -sdy : -s2dy);
            const float lf = __shfl_up_sync(FULLM, T1.y, 1);
            const float rt = __shfl_down_sync(FULLM, T1.x, 1);
            float2 A;
            A.x = T1.x - DTC * (uA.x * ((T1.y - lf) * iA)
                              + vA.x * (cA * T2.x + cB * T1.x + cC * T0.x)) * mA.x;
            A.y = T1.y - DTC * (uA.y * ((rt - T1.x) * iA)
                              + vA.y * (cA * T2.y + cB * T1.y + cC * T0.y)) * mA.y;
            float Am = __shfl_up_sync(FULLM, A.y, 1);
            float Ap = __shfl_down_sync(FULLM, A.x, 1);
            Am = zL ? 0.f : Am;
            Ap = zR ? 0.f : Ap;
            h1c.x = Am  + 2.f * A.x + A.y;
            h1c.y = A.x + 2.f * A.y + Ap;
        } else {
            h1c = f2z();
        }

        // ---- stage 2: vertical (1,2,1)/16 * mask -> F1 (step-1 output) at rF
        F1a = F1b; F1b = F1c;
        if (rF >= 0 && rF < HH) {
            F1c.x = (h1a.x + 2.f * h1b.x + h1c.x) * 0.0625f * m1.x;
            F1c.y = (h1a.y + 2.f * h1b.y + h1c.y) * 0.0625f * m1.y;
        } else {
            F1c = f2z();
        }

        // ---- stage 3: advection step 2 + horizontal (1,2,1) at row rB
        h2a = h2b; h2b = h2c;
        if (rB >= 0 && rB < HH) {
            const float cA = (rB == 0) ? sdy  : ((rB == HH - 1) ? 0.f  : s2dy);
            const float cB = (rB == 0) ? -sdy : ((rB == HH - 1) ? sdy  : 0.f);
            const float cC = (rB == 0) ? 0.f  : ((rB == HH - 1) ? -sdy : -s2dy);
            const float lf = __shfl_up_sync(FULLM, F1b.y, 1);
            const float rt = __shfl_down_sync(FULLM, F1b.x, 1);
            float2 A;
            A.x = F1b.x - DTC * (u2.x * ((F1b.y - lf) * i2)
                               + v2.x * (cA * F1c.x + cB * F1b.x + cC * F1a.x)) * m2.x;
            A.y = F1b.y - DTC * (u2.y * ((rt - F1b.x) * i2)
                               + v2.y * (cA * F1c.y + cB * F1b.y + cC * F1a.y)) * m2.y;
            float Am = __shfl_up_sync(FULLM, A.y, 1);
            float Ap = __shfl_down_sync(FULLM, A.x, 1);
            Am = zL ? 0.f : Am;
            Ap = zR ? 0.f : Ap;
            h2c.x = Am  + 2.f * A.x + A.y;
            h2c.y = A.x + 2.f * A.y + Ap;
        } else {
            h2c = f2z();
        }

        // ---- stage 4: vertical (1,2,1)/16 * mask -> final output at rE
        if (emitl && rE >= y0) {            // rE <= y0+TYS-1 by loop bound
            float2 o;
            o.x = (h2a.x + 2.f * h2b.x + h2c.x) * 0.0625f * m3.x;
            o.y = (h2a.y + 2.f * h2b.y + h2c.y) * 0.0625f * m3.y;
            Ob[(size_t)rE * W2 + c] = o;
        }

        // roll T
        T0 = T1; T1 = T2;
    }
}

extern "C" void kernel_launch(void* const* d_in, const int* in_sizes, int n_in,
                              void* d_out, int out_size)
{
    const float* T    = (const float*)d_in[0];
    const float* ug   = (const float*)d_in[1];
    const float* vg   = (const float*)d_in[2];
    const float* lat  = (const float*)d_in[3];
    const float* lon  = (const float*)d_in[4];
    const float* mask = (const float*)d_in[5];
    float* out = (float*)d_out;

    float *bufA = nullptr, *bufB = nullptr;
    cudaGetSymbolAddress((void**)&bufA, g_bufA);
    cudaGetSymbolAddress((void**)&bufB, g_bufB);

    const int nwarps = SEGS * BANDS * BB;       // 13*30*8 = 3120
    dim3 grid(nwarps / 4);                       // 780 blocks x 128 threads
    dim3 block(128);

    const float* cur = T;
    const int npairs = NSTEPS / 2;               // 10 fused launches
    for (int p = 0; p < npairs; ++p) {
        float* dst = (p == npairs - 1) ? out : ((p & 1) ? bufB : bufA);
        ocean_step2<<<grid, block>>>(cur, dst, ug, vg, lat, lon, mask);
        cur = dst;
    }
}

// round 6
// speedup vs baseline: 2.8686x; 1.2034x over previous
#include <cuda_runtime.h>

#define HH 360
#define WW 720
#define W2 360
#define BB 8
#define TYS 15
#define NITER (TYS + 6)       // 21
#define NTAB  (NITER + 2)     // 23 rows: y0-5 .. y0+TYS+2
#define SEGS 13               // 13*28 = 364 >= 360 float2 cols (wrap, dup writes identical)
#define BANDS (HH / TYS)      // 24
#define NSTEPS 20
#define FULLM 0xffffffffu

// Ping-pong scratch (allocation-free: __device__ globals).
__device__ float g_bufA[BB * HH * WW];
__device__ float g_bufB[BB * HH * WW];

__device__ __forceinline__ float2 f2z() { return make_float2(0.f, 0.f); }
__device__ __forceinline__ int rclamp(int r) { return min(max(r, 0), HH - 1); }

// Two fused timesteps, 6-stage rolling pipeline down y.
// IN=true: interior band — no clamps, no validity checks, central dT/dy only,
// loads become base+const-offset after full unroll.
template <bool IN>
__device__ __forceinline__ void run_band(
    const float2* __restrict__ Tb, const float2* __restrict__ ub,
    const float2* __restrict__ vb, const float2* __restrict__ mb,
    float2* __restrict__ Ob, const float* __restrict__ sI,
    const int y0, const int c, const bool emitl, const bool zL, const bool zR,
    const float sdy, const float s2dy)
{
    const float DTC = 600.0f;

    float2 T0, T1, TPf, uPf, vPf, mPf;
    {
        const int r0 = IN ? (y0 - 4) : rclamp(y0 - 4);
        const int r1 = IN ? (y0 - 3) : rclamp(y0 - 3);
        const int r2 = IN ? (y0 - 2) : rclamp(y0 - 2);
        T0  = Tb[r0 * W2 + c];
        T1  = Tb[r1 * W2 + c];
        TPf = Tb[r2 * W2 + c];
        uPf = ub[r1 * W2 + c];
        vPf = vb[r1 * W2 + c];
        mPf = mb[r1 * W2 + c];
    }

    float2 h1a = f2z(), h1b = f2z(), h1c = f2z();
    float2 F1a = f2z(), F1b = f2z(), F1c = f2z();
    float2 h2a = f2z(), h2b = f2z(), h2c = f2z();
    float2 uC = f2z(), u1 = f2z(), u2 = f2z();
    float2 vC = f2z(), v1 = f2z(), v2 = f2z();
    float2 mC = f2z(), m1 = f2z(), m2 = f2z(), m3 = f2z();

#pragma unroll
    for (int k = 0; k < NITER; ++k) {
        const int a = y0 - 3 + k;       // step-1 advection row

        // ring shifts (renamed by full unroll)
        m3 = m2; m2 = m1; m1 = mC;
        u2 = u1; u1 = uC;
        v2 = v1; v1 = vC;
        const float2 T2 = TPf;
        uC = uPf; vC = vPf; mC = mPf;

        // prefetch next iteration's rows (T: a+2, u/v/m: a+1)
        {
            const int rT = IN ? (a + 2) : rclamp(a + 2);
            const int rU = IN ? (a + 1) : rclamp(a + 1);
            TPf = Tb[rT * W2 + c];
            uPf = ub[rU * W2 + c];
            vPf = vb[rU * W2 + c];
            mPf = mb[rU * W2 + c];
        }

        // ---- stage 1: advection step 1 + horizontal (1,2,1) at row a
        h1a = h1b; h1b = h1c;
        {
            const float iA = sI[k + 2];
            float dty0, dty1;
            if (IN) {
                dty0 = (T2.x - T0.x) * s2dy;
                dty1 = (T2.y - T0.y) * s2dy;
            } else {
                const float cA = (a == 0) ? sdy  : ((a == HH - 1) ? 0.f  : s2dy);
                const float cB = (a == 0) ? -sdy : ((a == HH - 1) ? sdy  : 0.f);
                const float cC = (a == 0) ? 0.f  : ((a == HH - 1) ? -sdy : -s2dy);
                dty0 = cA * T2.x + cB * T1.x + cC * T0.x;
                dty1 = cA * T2.y + cB * T1.y + cC * T0.y;
            }
            const float lf = __shfl_up_sync(FULLM, T1.y, 1);
            const float rt = __shfl_down_sync(FULLM, T1.x, 1);
            const float A0 = T1.x - DTC * (uC.x * ((T1.y - lf) * iA) + vC.x * dty0) * mC.x;
            const float A1 = T1.y - DTC * (uC.y * ((rt - T1.x) * iA) + vC.y * dty1) * mC.y;
            float Am = __shfl_up_sync(FULLM, A1, 1);
            float Ap = __shfl_down_sync(FULLM, A0, 1);
            Am = zL ? 0.f : Am;
            Ap = zR ? 0.f : Ap;
            float hx = Am + 2.f * A0 + A1;
            float hy = A0 + 2.f * A1 + Ap;
            if (!IN && !(a >= 0 && a < HH)) { hx = 0.f; hy = 0.f; }
            h1c.x = hx; h1c.y = hy;
        }

        // ---- stage 2: vertical (1,2,1)/16 * mask -> F1 at row f = a-1
        F1a = F1b; F1b = F1c;
        {
            float fx = (h1a.x + 2.f * h1b.x + h1c.x) * 0.0625f * m1.x;
            float fy = (h1a.y + 2.f * h1b.y + h1c.y) * 0.0625f * m1.y;
            if (!IN) { const int f = a - 1; if (!(f >= 0 && f < HH)) { fx = 0.f; fy = 0.f; } }
            F1c.x = fx; F1c.y = fy;
        }

        // ---- stage 3: advection step 2 + horizontal (1,2,1) at row g = a-2
        h2a = h2b; h2b = h2c;
        {
            const int g = a - 2;
            const float iG = sI[k];
            float dty0, dty1;
            if (IN) {
                dty0 = (F1c.x - F1a.x) * s2dy;
                dty1 = (F1c.y - F1a.y) * s2dy;
            } else {
                const float cA = (g == 0) ? sdy  : ((g == HH - 1) ? 0.f  : s2dy);
                const float cB = (g == 0) ? -sdy : ((g == HH - 1) ? sdy  : 0.f);
                const float cC = (g == 0) ? 0.f  : ((g == HH - 1) ? -sdy : -s2dy);
                dty0 = cA * F1c.x + cB * F1b.x + cC * F1a.x;
                dty1 = cA * F1c.y + cB * F1b.y + cC * F1a.y;
            }
            const float lf = __shfl_up_sync(FULLM, F1b.y, 1);
            const float rt = __shfl_down_sync(FULLM, F1b.x, 1);
            const float A0 = F1b.x - DTC * (u2.x * ((F1b.y - lf) * iG) + v2.x * dty0) * m2.x;
            const float A1 = F1b.y - DTC * (u2.y * ((rt - F1b.x) * iG) + v2.y * dty1) * m2.y;
            float Am = __shfl_up_sync(FULLM, A1, 1);
            float Ap = __shfl_down_sync(FULLM, A0, 1);
            Am = zL ? 0.f : Am;
            Ap = zR ? 0.f : Ap;
            float hx = Am + 2.f * A0 + A1;
            float hy = A0 + 2.f * A1 + Ap;
            if (!IN && !(g >= 0 && g < HH)) { hx = 0.f; hy = 0.f; }
            h2c.x = hx; h2c.y = hy;
        }

        // ---- stage 4: vertical (1,2,1)/16 * mask -> emit row e = a-3
        if (k >= 6) {                       // compile-time prune of fill iters
            if (emitl) {
                const int e = a - 3;        // in [y0, y0+TYS)
                float2 o;
                o.x = (h2a.x + 2.f * h2b.x + h2c.x) * 0.0625f * m3.x;
                o.y = (h2a.y + 2.f * h2b.y + h2c.y) * 0.0625f * m3.y;
                Ob[e * W2 + c] = o;
            }
        }

        T0 = T1; T1 = T2;
    }
}

__global__ __launch_bounds__(128, 5) void ocean_step2(
    const float* __restrict__ Tin, float* __restrict__ Tout,
    const float* __restrict__ ug, const float* __restrict__ vg,
    const float* __restrict__ lat, const float* __restrict__ lon,
    const float* __restrict__ mask)
{
    __shared__ float sIw[4][NTAB];    // per-warp 1/(2dx) tables

    const int tid  = threadIdx.x;
    const int lane = tid & 31;
    const int wib  = tid >> 5;
    const int ws   = blockIdx.x * 4 + wib;
    const int seg  = ws % SEGS;
    const int rem  = ws / SEGS;
    const int band = rem % BANDS;
    const int b    = rem / BANDS;
    const int y0   = band * TYS;

    // lane -> float2 column (wrapped). Lanes 2..29 emit.
    int c = seg * 28 - 2 + lane;
    c += (c < 0) ? W2 : 0;
    c -= (c >= W2) ? W2 : 0;
    const bool emitl = (lane >= 2) && (lane <= 29);
    const bool zL = (c == 0);
    const bool zR = (c == W2 - 1);

    const float DEG2RAD = 0.017453292519943295f;
    const float RE = 6371000.0f;
    const float dlat = lat[1] - lat[0];
    const float dlon = lon[1] - lon[0];
    const float dy   = RE * DEG2RAD * fabsf(dlat);
    const float sgn  = (dlat > 0.f) ? 1.f : -1.f;
    const float sdy  = sgn / dy;
    const float s2dy = sgn / (2.f * dy);
    const float xden = 2.f * RE * DEG2RAD * dlon;

    // fill this warp's inv2dx table: rows y0-5 .. y0+TYS+2 (clamped)
    if (lane < NTAB) {
        const int r = rclamp(y0 - 5 + lane);
        sIw[wib][lane] = __fdividef(1.f, xden * __cosf(lat[r] * DEG2RAD));
    }
    __syncwarp();

    const float2* Tb = (const float2*)(Tin + (size_t)b * HH * WW);
    const float2* ub = (const float2*)(ug  + (size_t)b * HH * WW);
    const float2* vb = (const float2*)(vg  + (size_t)b * HH * WW);
    const float2* mb = (const float2*)mask;
    float2*       Ob = (float2*)(Tout + (size_t)b * HH * WW);
    const float*  sI = sIw[wib];

    // interior: all rows y0-5 .. y0+TYS+4 within [0, HH) and no y-boundary rows
    if (band > 0 && band < BANDS - 1)
        run_band<true >(Tb, ub, vb, mb, Ob, sI, y0, c, emitl, zL, zR, sdy, s2dy);
    else
        run_band<false>(Tb, ub, vb, mb, Ob, sI, y0, c, emitl, zL, zR, sdy, s2dy);
}

extern "C" void kernel_launch(void* const* d_in, const int* in_sizes, int n_in,
                              void* d_out, int out_size)
{
    const float* T    = (const float*)d_in[0];
    const float* ug   = (const float*)d_in[1];
    const float* vg   = (const float*)d_in[2];
    const float* lat  = (const float*)d_in[3];
    const float* lon  = (const float*)d_in[4];
    const float* mask = (const float*)d_in[5];
    float* out = (float*)d_out;

    float *bufA = nullptr, *bufB = nullptr;
    cudaGetSymbolAddress((void**)&bufA, g_bufA);
    cudaGetSymbolAddress((void**)&bufB, g_bufB);

    const int nwarps = SEGS * BANDS * BB;   // 13*24*8 = 2496
    dim3 grid(nwarps / 4);                  // 624 blocks
    dim3 block(128);

    const float* cur = T;
    const int npairs = NSTEPS / 2;          // 10 fused launches
    for (int p = 0; p < npairs; ++p) {
        float* dst = (p == npairs - 1) ? out : ((p & 1) ? bufB : bufA);
        ocean_step2<<<grid, block>>>(cur, dst, ug, vg, lat, lon, mask);
        cur = dst;
    }
}